// round 2
// baseline (speedup 1.0000x reference)
#include <cuda_runtime.h>
#include <cuda_bf16.h>
#include <cstdint>

// Scratch: per-node projections. P[n][0..9]  = h[n] . W_w[c, 0:128]   (src half)
//          P[n][10..19] = h[n] . W_w[c, 128:256] (dst half)
#define N_NODES_MAX 100000
__device__ float g_P[N_NODES_MAX * 20];
__device__ int   g_idx_is64;

// ---------------------------------------------------------------------------
// Kernel 0: probe index dtype. int64 node ids (<100000) have hi-word == 0.
// int32 data read as int64 puts a random node id in the hi-word.
// ---------------------------------------------------------------------------
__global__ void probe_idx_kernel(const long long* __restrict__ src) {
    if (threadIdx.x == 0 && blockIdx.x == 0) {
        int is64 = 1;
        for (int i = 0; i < 8; i++) {
            long long v = src[i];                 // 64B read: in-bounds either way
            if ((unsigned long long)v >> 32) is64 = 0;
        }
        g_idx_is64 = is64;
    }
}

// ---------------------------------------------------------------------------
// Kernel 1: node projections. Warp per node, grid-stride.
// h: [N,128], W_w: [10, 384] row-major.
// ---------------------------------------------------------------------------
__global__ void node_proj_kernel(const float* __restrict__ h,
                                 const float* __restrict__ W_w,
                                 int n_nodes) {
    __shared__ float sW[20][128]; // rows 0-9: W_u, rows 10-19: W_v
    int tid = threadIdx.x;
    for (int i = tid; i < 20 * 128; i += blockDim.x) {
        int c = i >> 7, k = i & 127;
        sW[c][k] = (c < 10) ? W_w[c * 384 + k]
                            : W_w[(c - 10) * 384 + 128 + k];
    }
    __syncthreads();

    int lane   = tid & 31;
    int warp   = (blockIdx.x * blockDim.x + tid) >> 5;
    int nwarps = (gridDim.x * blockDim.x) >> 5;

    float4 w[20];
#pragma unroll
    for (int c = 0; c < 20; c++)
        w[c] = reinterpret_cast<const float4*>(sW[c])[lane];

    for (int n = warp; n < n_nodes; n += nwarps) {
        float4 x = reinterpret_cast<const float4*>(h + (size_t)n * 128)[lane];
        float acc[20];
#pragma unroll
        for (int c = 0; c < 20; c++)
            acc[c] = x.x * w[c].x + x.y * w[c].y + x.z * w[c].z + x.w * w[c].w;

#pragma unroll
        for (int off = 16; off > 0; off >>= 1) {
#pragma unroll
            for (int c = 0; c < 20; c++)
                acc[c] += __shfl_xor_sync(0xffffffffu, acc[c], off);
        }

        // lanes 0..19 each store one channel: coalesced 80B row store
        float oval = acc[0];
#pragma unroll
        for (int c = 1; c < 20; c++)
            if (lane == c) oval = acc[c];
        if (lane < 20)
            g_P[(size_t)n * 20 + lane] = oval;
    }
}

// ---------------------------------------------------------------------------
// Kernel 2: per-edge. out[e][c] = P[src[e]][c] + P[dst[e]][10+c]
//                                + edge_h[e] . W_e[c] + b[c]
// Warp per edge, grid-stride. edge_h: [E,128] f32.
// ---------------------------------------------------------------------------
__global__ void edge_kernel(const float* __restrict__ eh,
                            const float* __restrict__ W_w,
                            const float* __restrict__ W_b,
                            const void* __restrict__ src_raw,
                            const void* __restrict__ dst_raw,
                            float* __restrict__ out,
                            int n_edges) {
    __shared__ float sW[10][128];
    __shared__ float sb[10];
    int tid = threadIdx.x;
    for (int i = tid; i < 10 * 128; i += blockDim.x) {
        int c = i >> 7, k = i & 127;
        sW[c][k] = W_w[c * 384 + 256 + k];
    }
    if (tid < 10) sb[tid] = W_b[tid];
    __syncthreads();

    const int is64 = g_idx_is64;
    int lane   = tid & 31;
    int warp   = (blockIdx.x * blockDim.x + tid) >> 5;
    int nwarps = (gridDim.x * blockDim.x) >> 5;

    float4 w[10];
#pragma unroll
    for (int c = 0; c < 10; c++)
        w[c] = reinterpret_cast<const float4*>(sW[c])[lane];
    float blane = (lane < 10) ? sb[lane] : 0.0f;

    for (int e = warp; e < n_edges; e += nwarps) {
        float4 x = reinterpret_cast<const float4*>(eh + (size_t)e * 128)[lane];
        float acc[10];
#pragma unroll
        for (int c = 0; c < 10; c++)
            acc[c] = x.x * w[c].x + x.y * w[c].y + x.z * w[c].z + x.w * w[c].w;

#pragma unroll
        for (int off = 16; off > 0; off >>= 1) {
#pragma unroll
            for (int c = 0; c < 10; c++)
                acc[c] += __shfl_xor_sync(0xffffffffu, acc[c], off);
        }

        // indices (uniform branch across warp)
        long long s, d;
        if (is64) {
            s = ((const long long*)src_raw)[e];
            d = ((const long long*)dst_raw)[e];
        } else {
            s = ((const int*)src_raw)[e];
            d = ((const int*)dst_raw)[e];
        }

        // channel select: lane c takes acc[c] (predicated moves, no spill)
        float oval = acc[0];
#pragma unroll
        for (int c = 1; c < 10; c++)
            if (lane == c) oval = acc[c];

        if (lane < 10) {
            float pu = __ldg(g_P + (size_t)s * 20 + lane);       // channels 0..9
            float pv = __ldg(g_P + (size_t)d * 20 + 10 + lane);  // channels 10..19
            out[(size_t)e * 10 + lane] = oval + pu + pv + blane;
        }
    }
}

// ---------------------------------------------------------------------------
// Inputs (metadata order): h [100000,128] f32, edge_h [600000,1,128] f32,
// W_w [10,384] f32, W_b [10] f32, src [600000] int, dst [600000] int.
// Output: [600000,10] f32.
// ---------------------------------------------------------------------------
extern "C" void kernel_launch(void* const* d_in, const int* in_sizes, int n_in,
                              void* d_out, int out_size) {
    const float* h    = (const float*)d_in[0];
    const float* eh   = (const float*)d_in[1];
    const float* W_w  = (const float*)d_in[2];
    const float* W_b  = (const float*)d_in[3];
    const void*  src  = d_in[4];
    const void*  dst  = d_in[5];
    float*       out  = (float*)d_out;

    int n_nodes = in_sizes[0] / 128;
    int n_edges = in_sizes[4];

    probe_idx_kernel<<<1, 32>>>((const long long*)src);

    node_proj_kernel<<<1024, 256>>>(h, W_w, n_nodes);

    edge_kernel<<<2368, 256>>>(eh, W_w, W_b, src, dst, out, n_edges);
}

// round 4
// speedup vs baseline: 1.3942x; 1.3942x over previous
#include <cuda_runtime.h>
#include <cstdint>

// Padded per-node projections: row stride 32 floats.
//   [n*32 + 0 .. 9]  = h[n] . W_u[c]   (src half of W)
//   [n*32 + 16 ..25] = h[n] . W_v[c]   (dst half of W)
// 100000 * 32 * 4B = 12.8 MB. __device__ global => allocation-free.
#define N_NODES_MAX 100000
__device__ float g_P[N_NODES_MAX * 32];
__device__ int   g_idx_is64;

// packed dual-FMA (Blackwell f32x2 pipe)
__device__ __forceinline__ float2 ffma2(float2 a, float2 b, float2 c) {
    float2 d;
    asm("{\n\t"
        ".reg .b64 ra, rb, rc, rd;\n\t"
        "mov.b64 ra, {%2, %3};\n\t"
        "mov.b64 rb, {%4, %5};\n\t"
        "mov.b64 rc, {%6, %7};\n\t"
        "fma.rn.f32x2 rd, ra, rb, rc;\n\t"
        "mov.b64 {%0, %1}, rd;\n\t"
        "}"
        : "=f"(d.x), "=f"(d.y)
        : "f"(a.x), "f"(a.y), "f"(b.x), "f"(b.y), "f"(c.x), "f"(c.y));
    return d;
}

// ---------------------------------------------------------------------------
// Kernel 0: probe index dtype (int64 node ids < 100000 have zero hi-words).
// ---------------------------------------------------------------------------
__global__ void probe_idx_kernel(const long long* __restrict__ src) {
    if (threadIdx.x == 0 && blockIdx.x == 0) {
        int is64 = 1;
        for (int i = 0; i < 8; i++) {
            long long v = src[i];
            if ((unsigned long long)v >> 32) is64 = 0;
        }
        g_idx_is64 = is64;
    }
}

// ---------------------------------------------------------------------------
// Kernel 1: node projections. Thread-per-node, smem-staged tile of 128 nodes.
// h: [N,128], W_w: [10,384]. 20 output channels = 10 float2 pairs.
// ---------------------------------------------------------------------------
#define NTILE 128
__global__ void node_kernel(const float* __restrict__ h,
                            const float* __restrict__ W_w,
                            int n_nodes) {
    extern __shared__ float4 sH[];          // NTILE*32 float4 = 64 KB, swizzled
    __shared__ float2 sW2[32][10][4];       // [k][pair][comp], 10 KB
    int tid = threadIdx.x;

    for (int i = tid; i < 32 * 10 * 4; i += NTILE) {
        int k = i / 40, r = i % 40, p = r / 4, comp = r % 4;
        int c0  = (p < 5) ? 2 * p : 2 * (p - 5);
        int col = ((p < 5) ? 0 : 128) + k * 4 + comp;
        sW2[k][p][comp] = make_float2(W_w[c0 * 384 + col],
                                      W_w[(c0 + 1) * 384 + col]);
    }

    long long tile0 = (long long)blockIdx.x * NTILE;
    int navail = n_nodes - (int)tile0; if (navail > NTILE) navail = NTILE;
    int nf4 = navail * 32;
    const float4* hb = (const float4*)h + tile0 * 32;
#pragma unroll 4
    for (int i = tid; i < NTILE * 32; i += NTILE) {
        float4 v = (i < nf4) ? __ldg(hb + i) : make_float4(0, 0, 0, 0);
        int e = i >> 5, k = i & 31;
        sH[e * 32 + (k ^ (e & 31))] = v;
    }
    __syncthreads();

    long long n = tile0 + tid;
    if (n >= n_nodes) return;

    float2 acc[10];
#pragma unroll
    for (int p = 0; p < 10; p++) acc[p] = make_float2(0.f, 0.f);
    int swz = tid & 31;
#pragma unroll
    for (int k = 0; k < 32; k++) {
        float4 x = sH[tid * 32 + (k ^ swz)];
        float2 x0 = make_float2(x.x, x.x), x1 = make_float2(x.y, x.y);
        float2 x2 = make_float2(x.z, x.z), x3 = make_float2(x.w, x.w);
#pragma unroll
        for (int p = 0; p < 10; p++) {
            float4 wab = *(const float4*)&sW2[k][p][0];   // comps 0,1
            float4 wcd = *(const float4*)&sW2[k][p][2];   // comps 2,3
            acc[p] = ffma2(x0, make_float2(wab.x, wab.y), acc[p]);
            acc[p] = ffma2(x1, make_float2(wab.z, wab.w), acc[p]);
            acc[p] = ffma2(x2, make_float2(wcd.x, wcd.y), acc[p]);
            acc[p] = ffma2(x3, make_float2(wcd.z, wcd.w), acc[p]);
        }
    }
    float* pb = g_P + n * 32;
#pragma unroll
    for (int p = 0; p < 5; p++)  ((float2*)pb)[p]        = acc[p];
#pragma unroll
    for (int p = 5; p < 10; p++) ((float2*)(pb + 16))[p - 5] = acc[p];
}

// ---------------------------------------------------------------------------
// Kernel 2: per-edge. Thread-per-edge, smem-staged tile of 128 edges.
// out[e][c] = edge_h[e].W_e[c] + P[src][c] + P[dst][16+c] + b[c]
// ---------------------------------------------------------------------------
#define ETILE 128
__global__ void edge_kernel(const float* __restrict__ eh,
                            const float* __restrict__ W_w,
                            const float* __restrict__ W_b,
                            const void* __restrict__ src_raw,
                            const void* __restrict__ dst_raw,
                            float* __restrict__ out,
                            int n_edges) {
    extern __shared__ float4 sEH[];         // ETILE*32 float4 = 64 KB, swizzled
    __shared__ float2 sW2[32][5][4];        // [k][pair][comp], 5 KB
    __shared__ float2 sB[5];
    int tid = threadIdx.x;

    for (int i = tid; i < 32 * 5 * 4; i += ETILE) {
        int k = i / 20, r = i % 20, p = r / 4, comp = r % 4;
        int col = 256 + k * 4 + comp;
        sW2[k][p][comp] = make_float2(W_w[(2 * p) * 384 + col],
                                      W_w[(2 * p + 1) * 384 + col]);
    }
    if (tid < 5) sB[tid] = make_float2(W_b[2 * tid], W_b[2 * tid + 1]);

    long long tile0 = (long long)blockIdx.x * ETILE;
    int navail = n_edges - (int)tile0; if (navail > ETILE) navail = ETILE;
    int nf4 = navail * 32;
    const float4* ehb = (const float4*)eh + tile0 * 32;
#pragma unroll 4
    for (int i = tid; i < ETILE * 32; i += ETILE) {
        float4 v = (i < nf4) ? __ldg(ehb + i) : make_float4(0, 0, 0, 0);
        int e = i >> 5, k = i & 31;
        sEH[e * 32 + (k ^ (e & 31))] = v;
    }
    __syncthreads();

    long long e = tile0 + tid;
    if (e >= n_edges) return;

    float2 acc[5];
#pragma unroll
    for (int p = 0; p < 5; p++) acc[p] = make_float2(0.f, 0.f);
    int swz = tid & 31;
#pragma unroll
    for (int k = 0; k < 32; k++) {
        float4 x = sEH[tid * 32 + (k ^ swz)];
        float2 x0 = make_float2(x.x, x.x), x1 = make_float2(x.y, x.y);
        float2 x2 = make_float2(x.z, x.z), x3 = make_float2(x.w, x.w);
#pragma unroll
        for (int p = 0; p < 5; p++) {
            float4 wab = *(const float4*)&sW2[k][p][0];
            float4 wcd = *(const float4*)&sW2[k][p][2];
            acc[p] = ffma2(x0, make_float2(wab.x, wab.y), acc[p]);
            acc[p] = ffma2(x1, make_float2(wab.z, wab.w), acc[p]);
            acc[p] = ffma2(x2, make_float2(wcd.x, wcd.y), acc[p]);
            acc[p] = ffma2(x3, make_float2(wcd.z, wcd.w), acc[p]);
        }
    }

    long long s, d;
    if (g_idx_is64) {
        s = ((const long long*)src_raw)[e];
        d = ((const long long*)dst_raw)[e];
    } else {
        s = ((const int*)src_raw)[e];
        d = ((const int*)dst_raw)[e];
    }
    const float4* pu = (const float4*)(g_P + s * 32);        // ch 0..9
    const float4* pv = (const float4*)(g_P + d * 32 + 16);   // ch 0..9 (dst)
    float4 ua = __ldg(pu),  ub = __ldg(pu + 1);
    float2 uc = __ldg((const float2*)(pu + 2));
    float4 va = __ldg(pv),  vb = __ldg(pv + 1);
    float2 vc = __ldg((const float2*)(pv + 2));

    float2 r0 = make_float2(acc[0].x + ua.x + va.x + sB[0].x,
                            acc[0].y + ua.y + va.y + sB[0].y);
    float2 r1 = make_float2(acc[1].x + ua.z + va.z + sB[1].x,
                            acc[1].y + ua.w + va.w + sB[1].y);
    float2 r2 = make_float2(acc[2].x + ub.x + vb.x + sB[2].x,
                            acc[2].y + ub.y + vb.y + sB[2].y);
    float2 r3 = make_float2(acc[3].x + ub.z + vb.z + sB[3].x,
                            acc[3].y + ub.w + vb.w + sB[3].y);
    float2 r4 = make_float2(acc[4].x + uc.x + vc.x + sB[4].x,
                            acc[4].y + uc.y + vc.y + sB[4].y);

    float2* op = (float2*)(out + e * 10);
    op[0] = r0; op[1] = r1; op[2] = r2; op[3] = r3; op[4] = r4;
}

// ---------------------------------------------------------------------------
// Inputs: h [100000,128] f32, edge_h [600000,1,128] f32, W_w [10,384] f32,
// W_b [10] f32, src [600000] int32/64, dst [600000] int32/64.
// Output: [600000,10] f32.
// ---------------------------------------------------------------------------
extern "C" void kernel_launch(void* const* d_in, const int* in_sizes, int n_in,
                              void* d_out, int out_size) {
    const float* h   = (const float*)d_in[0];
    const float* eh  = (const float*)d_in[1];
    const float* W_w = (const float*)d_in[2];
    const float* W_b = (const float*)d_in[3];
    const void*  src = d_in[4];
    const void*  dst = d_in[5];
    float*       out = (float*)d_out;

    int n_nodes = in_sizes[0] / 128;
    int n_edges = in_sizes[4];

    cudaFuncSetAttribute(node_kernel,
                         cudaFuncAttributeMaxDynamicSharedMemorySize, 65536);
    cudaFuncSetAttribute(edge_kernel,
                         cudaFuncAttributeMaxDynamicSharedMemorySize, 65536);

    probe_idx_kernel<<<1, 32>>>((const long long*)src);

    int nblk = (n_nodes + NTILE - 1) / NTILE;
    node_kernel<<<nblk, NTILE, 65536>>>(h, W_w, n_nodes);

    int eblk = (n_edges + ETILE - 1) / ETILE;
    edge_kernel<<<eblk, ETILE, 65536>>>(eh, W_w, W_b, src, dst, out, n_edges);
}

// round 6
// speedup vs baseline: 1.6647x; 1.1940x over previous
#include <cuda_runtime.h>
#include <cstdint>

// Padded per-node projections: row stride 32 floats.
//   [n*32 + 0..9]   = h[n].W_u[c]  (src half of W)
//   [n*32 + 16..25] = h[n].W_v[c]  (dst half of W)
#define N_NODES_MAX 100000
__device__ float g_P[N_NODES_MAX * 32];
__device__ int   g_idx_is64;

__device__ __forceinline__ float2 ffma2(float2 a, float2 b, float2 c) {
    float2 d;
    asm("{\n\t"
        ".reg .b64 ra, rb, rc, rd;\n\t"
        "mov.b64 ra, {%2, %3};\n\t"
        "mov.b64 rb, {%4, %5};\n\t"
        "mov.b64 rc, {%6, %7};\n\t"
        "fma.rn.f32x2 rd, ra, rb, rc;\n\t"
        "mov.b64 {%0, %1}, rd;\n\t"
        "}"
        : "=f"(d.x), "=f"(d.y)
        : "f"(a.x), "f"(a.y), "f"(b.x), "f"(b.y), "f"(c.x), "f"(c.y));
    return d;
}

__device__ __forceinline__ void cp_async16(uint32_t dst, const void* src, int pred) {
    asm volatile(
        "{\n\t.reg .pred p;\n\t"
        "setp.ne.b32 p, %0, 0;\n\t"
        "@p cp.async.cg.shared.global [%1], [%2], 16;\n\t}"
        :: "r"(pred), "r"(dst), "l"(src));
}
#define CP_COMMIT() asm volatile("cp.async.commit_group;" ::: "memory")
#define CP_WAIT1()  asm volatile("cp.async.wait_group 1;" ::: "memory")

#define WPB 8  // warps per block (blockDim = 256)

// ---------------------------------------------------------------------------
// Node kernel: warp-autonomous tiles of 8 nodes, cp.async double-buffered.
// Lane split: esub = lane>>2 (node within tile), q = lane&3 (quarter-row).
// 20 channels = 10 float2 pairs. Also performs the index-dtype probe.
// ---------------------------------------------------------------------------
__global__ __launch_bounds__(256) void node_kernel(
    const float* __restrict__ h, const float* __restrict__ W_w,
    const long long* __restrict__ src_probe, int n_nodes) {
    extern __shared__ float4 smem4[];
    int tid = threadIdx.x, wid = tid >> 5, lane = tid & 31;

    if (blockIdx.x == 0 && tid == 0) {   // probe (node kernel precedes edge kernel)
        int is64 = 1;
        for (int i = 0; i < 8; i++)
            if ((unsigned long long)src_probe[i] >> 32) is64 = 0;
        g_idx_is64 = is64;
    }

    float4* sbuf = smem4 + wid * 512;            // 2 stages x 256 float4
    float4* sWa  = smem4 + WPB * 512;            // [j][p][q], 320 f4
    float4* sWb  = sWa + 320;
    for (int i = tid; i < 320; i += 256) {
        int j = i / 40, r = i % 40, p = r / 4, qq = r % 4;
        int base = (p < 5) ? 0 : 128;
        int c0   = (p < 5) ? 2 * p : 2 * (p - 5);
        int col  = base + qq * 32 + j * 4;
        const float* w0 = W_w + c0 * 384 + col;
        const float* w1 = W_w + (c0 + 1) * 384 + col;
        sWa[i] = make_float4(w0[0], w0[1], w0[2], w0[3]);
        sWb[i] = make_float4(w1[0], w1[1], w1[2], w1[3]);
    }
    __syncthreads();

    uint32_t sbase = (uint32_t)__cvta_generic_to_shared(sbuf);
    int q = lane & 3, esub = lane >> 2;
    long long T  = ((long long)n_nodes + 7) >> 3;
    long long gw = (long long)blockIdx.x * WPB + wid;
    long long nw = (long long)gridDim.x * WPB;

    // prologue issue
    {
        long long t = gw;
        if (t < T) {
            const float4* g = (const float4*)h + t * 256;
            long long rem = (long long)n_nodes * 32 - t * 256;
#pragma unroll
            for (int tt = 0; tt < 8; tt++) {
                int u = tt * 32 + lane;
                cp_async16(sbase + (uint32_t)((tt * 32 + (lane ^ tt)) * 16),
                           g + u, u < rem);
            }
        }
        CP_COMMIT();
    }

    int s = 0;
    for (long long t = gw; t < T; t += nw) {
        long long tn = t + nw;
        if (tn < T) {
            const float4* g = (const float4*)h + tn * 256;
            long long rem = (long long)n_nodes * 32 - tn * 256;
            uint32_t sb = sbase + (uint32_t)((s ^ 1) * 256 * 16);
#pragma unroll
            for (int tt = 0; tt < 8; tt++) {
                int u = tt * 32 + lane;
                cp_async16(sb + (uint32_t)((tt * 32 + (lane ^ tt)) * 16),
                           g + u, u < rem);
            }
        }
        CP_COMMIT();
        CP_WAIT1();
        __syncwarp();

        const float4* st = sbuf + s * 256;
        float2 acc[10];
#pragma unroll
        for (int p = 0; p < 10; p++) acc[p] = make_float2(0.f, 0.f);
#pragma unroll
        for (int j = 0; j < 8; j++) {
            float4 x = st[esub * 32 + (((q << 3) + j) ^ esub)];
#pragma unroll
            for (int p = 0; p < 10; p++) {
                float4 wa = sWa[j * 40 + p * 4 + q];
                float4 wb = sWb[j * 40 + p * 4 + q];
                acc[p] = ffma2(make_float2(x.x, x.x), make_float2(wa.x, wb.x), acc[p]);
                acc[p] = ffma2(make_float2(x.y, x.y), make_float2(wa.y, wb.y), acc[p]);
                acc[p] = ffma2(make_float2(x.z, x.z), make_float2(wa.z, wb.z), acc[p]);
                acc[p] = ffma2(make_float2(x.w, x.w), make_float2(wa.w, wb.w), acc[p]);
            }
        }
#pragma unroll
        for (int off = 1; off <= 2; off <<= 1)
#pragma unroll
            for (int p = 0; p < 10; p++) {
                acc[p].x += __shfl_xor_sync(0xffffffffu, acc[p].x, off);
                acc[p].y += __shfl_xor_sync(0xffffffffu, acc[p].y, off);
            }

        long long n = t * 8 + esub;
        if (n < n_nodes) {
            float2 pa = acc[0], pb = acc[5];
            if (q == 1) { pa = acc[1]; pb = acc[6]; }
            if (q == 2) { pa = acc[2]; pb = acc[7]; }
            if (q == 3) { pa = acc[3]; pb = acc[8]; }
            float* row = g_P + n * 32;
            *(float2*)(row + 2 * q)      = pa;
            *(float2*)(row + 16 + 2 * q) = pb;
            if (q == 0) {
                *(float2*)(row + 8)  = acc[4];
                *(float2*)(row + 24) = acc[9];
            }
        }
        s ^= 1;
    }
}

// ---------------------------------------------------------------------------
// Edge kernel: warp-autonomous tiles of 8 edges, cp.async double-buffered.
// out[e][c] = edge_h[e].W_e[c] + P[src][c] + P[dst][16+c] + b[c]
// ---------------------------------------------------------------------------
__global__ __launch_bounds__(256) void edge_kernel(
    const float* __restrict__ eh, const float* __restrict__ W_w,
    const float* __restrict__ W_b,
    const void* __restrict__ src_raw, const void* __restrict__ dst_raw,
    float* __restrict__ out, int n_edges) {
    extern __shared__ float4 smem4[];
    int tid = threadIdx.x, wid = tid >> 5, lane = tid & 31;

    float4* sbuf = smem4 + wid * 512;
    float4* sWa  = smem4 + WPB * 512;            // [j][p][q], 160 f4
    float4* sWb  = sWa + 160;
    for (int i = tid; i < 160; i += 256) {
        int j = i / 20, r = i % 20, p = r / 4, qq = r % 4;
        int col = 256 + qq * 32 + j * 4;
        const float* w0 = W_w + (2 * p) * 384 + col;
        const float* w1 = W_w + (2 * p + 1) * 384 + col;
        sWa[i] = make_float4(w0[0], w0[1], w0[2], w0[3]);
        sWb[i] = make_float4(w1[0], w1[1], w1[2], w1[3]);
    }
    __syncthreads();

    uint32_t sbase = (uint32_t)__cvta_generic_to_shared(sbuf);
    int q = lane & 3, esub = lane >> 2;
    int is64 = g_idx_is64;
    float2 bq = make_float2(W_b[2 * q], W_b[2 * q + 1]);
    float2 b4 = make_float2(W_b[8], W_b[9]);

    long long T  = ((long long)n_edges + 7) >> 3;
    long long gw = (long long)blockIdx.x * WPB + wid;
    long long nw = (long long)gridDim.x * WPB;

    {
        long long t = gw;
        if (t < T) {
            const float4* g = (const float4*)eh + t * 256;
            long long rem = (long long)n_edges * 32 - t * 256;
#pragma unroll
            for (int tt = 0; tt < 8; tt++) {
                int u = tt * 32 + lane;
                cp_async16(sbase + (uint32_t)((tt * 32 + (lane ^ tt)) * 16),
                           g + u, u < rem);
            }
        }
        CP_COMMIT();
    }

    int s = 0;
    for (long long t = gw; t < T; t += nw) {
        long long tn = t + nw;
        if (tn < T) {
            const float4* g = (const float4*)eh + tn * 256;
            long long rem = (long long)n_edges * 32 - tn * 256;
            uint32_t sb = sbase + (uint32_t)((s ^ 1) * 256 * 16);
#pragma unroll
            for (int tt = 0; tt < 8; tt++) {
                int u = tt * 32 + lane;
                cp_async16(sb + (uint32_t)((tt * 32 + (lane ^ tt)) * 16),
                           g + u, u < rem);
            }
        }
        CP_COMMIT();
        CP_WAIT1();
        __syncwarp();

        const float4* st = sbuf + s * 256;
        float2 acc[5];
#pragma unroll
        for (int p = 0; p < 5; p++) acc[p] = make_float2(0.f, 0.f);
#pragma unroll
        for (int j = 0; j < 8; j++) {
            float4 x = st[esub * 32 + (((q << 3) + j) ^ esub)];
#pragma unroll
            for (int p = 0; p < 5; p++) {
                float4 wa = sWa[j * 20 + p * 4 + q];
                float4 wb = sWb[j * 20 + p * 4 + q];
                acc[p] = ffma2(make_float2(x.x, x.x), make_float2(wa.x, wb.x), acc[p]);
                acc[p] = ffma2(make_float2(x.y, x.y), make_float2(wa.y, wb.y), acc[p]);
                acc[p] = ffma2(make_float2(x.z, x.z), make_float2(wa.z, wb.z), acc[p]);
                acc[p] = ffma2(make_float2(x.w, x.w), make_float2(wa.w, wb.w), acc[p]);
            }
        }
#pragma unroll
        for (int off = 1; off <= 2; off <<= 1)
#pragma unroll
            for (int p = 0; p < 5; p++) {
                acc[p].x += __shfl_xor_sync(0xffffffffu, acc[p].x, off);
                acc[p].y += __shfl_xor_sync(0xffffffffu, acc[p].y, off);
            }

        long long e = t * 8 + esub;
        if (e < n_edges) {
            long long sN, dN;
            if (is64) {
                sN = ((const long long*)src_raw)[e];
                dN = ((const long long*)dst_raw)[e];
            } else {
                sN = ((const int*)src_raw)[e];
                dN = ((const int*)dst_raw)[e];
            }
            const float2* pu = (const float2*)(g_P + sN * 32);
            const float2* pv = (const float2*)(g_P + dN * 32 + 16);
            float2 mya = acc[0];
            if (q == 1) mya = acc[1];
            if (q == 2) mya = acc[2];
            if (q == 3) mya = acc[3];
            float2 gu = __ldg(pu + q);
            float2 gv = __ldg(pv + q);
            *(float2*)(out + e * 10 + 2 * q) =
                make_float2(mya.x + gu.x + gv.x + bq.x,
                            mya.y + gu.y + gv.y + bq.y);
            if (q == 0) {
                float2 gu4 = __ldg(pu + 4);
                float2 gv4 = __ldg(pv + 4);
                *(float2*)(out + e * 10 + 8) =
                    make_float2(acc[4].x + gu4.x + gv4.x + b4.x,
                                acc[4].y + gu4.y + gv4.y + b4.y);
            }
        }
        s ^= 1;
    }
}

// ---------------------------------------------------------------------------
// Inputs: h [100000,128] f32, edge_h [600000,1,128] f32, W_w [10,384] f32,
// W_b [10] f32, src [600000] int32/64, dst [600000] int32/64.
// Output: [600000,10] f32.
// ---------------------------------------------------------------------------
extern "C" void kernel_launch(void* const* d_in, const int* in_sizes, int n_in,
                              void* d_out, int out_size) {
    const float* h   = (const float*)d_in[0];
    const float* eh  = (const float*)d_in[1];
    const float* W_w = (const float*)d_in[2];
    const float* W_b = (const float*)d_in[3];
    const void*  src = d_in[4];
    const void*  dst = d_in[5];
    float*       out = (float*)d_out;

    int n_nodes = in_sizes[0] / 128;
    int n_edges = in_sizes[4];

    int node_smem = (WPB * 512 + 640) * 16;   // 75,776 B
    int edge_smem = (WPB * 512 + 320) * 16;   // 70,656 B
    cudaFuncSetAttribute(node_kernel,
                         cudaFuncAttributeMaxDynamicSharedMemorySize, node_smem);
    cudaFuncSetAttribute(edge_kernel,
                         cudaFuncAttributeMaxDynamicSharedMemorySize, edge_smem);

    node_kernel<<<296, 256, node_smem>>>(h, W_w, (const long long*)src, n_nodes);
    edge_kernel<<<1184, 256, edge_smem>>>(eh, W_w, W_b, src, dst, out, n_edges);
}